// round 2
// baseline (speedup 1.0000x reference)
#include <cuda_runtime.h>

// ---------------- fixed problem sizes ----------------
#define BB   2
#define LL   1024
#define DIMM 128
#define EE   256
#define NN   16
#define RR   8
#define MIDC 16
#define HH   32
#define WW   32

// ---------------- device scratch (no allocs allowed) ----------------
__device__ float  g_xz[BB*LL*2*EE];      // [b][l][512]  (xm | z)
__device__ float  g_h1[BB*MIDC*LL];      // [b][m][l]
__device__ float  g_h2[BB*MIDC*LL];      // [b][m][l]
__device__ float  g_xconv[BB*LL*EE];     // [b][l][e]
__device__ float  g_delta[BB*LL*EE];     // [b][l][e]  softplus(dt + 2*bias)
__device__ float  g_dtlr[BB*LL*RR];
__device__ float  g_Bssm[BB*LL*NN];
__device__ float  g_Cssm[BB*LL*NN];
__device__ float  g_A[EE*NN];            // -exp(A_log)
__device__ int    g_order[4*LL];         // order[k][pos] = grid idx
__device__ int    g_code[4*LL];          // raw appended dir code at pos
__device__ float2 g_du[4*BB*LL*EE];      // (delta, u) gathered, [k][b][p][e]
__device__ float2 g_bc[4*BB*LL*NN];      // (B+dirB, C) gathered, [k][b][p][n]
__device__ float  g_yo[4*BB*LL*EE];      // scan outputs per direction
__device__ float  g_t[BB*LL*EE];         // (sum_k y)*silu(z)

__device__ __forceinline__ float sigmoidf_(float x){ return 1.f/(1.f+__expf(-x)); }

// ---------------- setup: A = -exp(A_log); scan orders (closed form, H=W=32) ----
__global__ void ss2d_setup(const float* __restrict__ A_log)
{
    int t = blockIdx.x*256 + threadIdx.x;
    if (t < EE*NN) g_A[t] = -__expf(A_log[t]);
    if (t < LL) {
        int i = t >> 5, j = t & 31;
        // k=0: row boustrophedon from bottom, start (31,0) going right
        {
            int r = 31 - i;
            int pos = r*32 + (((r&1)==0) ? j : 31-j);
            int c   = ((r&1)==0) ? (j<31?1:3) : (j>0?2:3);
            g_order[pos] = t; g_code[pos] = c;
        }
        // k=1: column boustrophedon, start (0,0) going down
        {
            int pos = j*32 + (((j&1)==0) ? i : 31-i);
            int c   = ((j&1)==0) ? (i<31?4:1) : (i>0?3:1);
            g_order[LL+pos] = t; g_code[LL+pos] = c;
        }
        // k=2: zigzag anti-diagonals
        {
            int dg  = i + j;
            int cum = (dg<=31) ? dg*(dg+1)/2 : 1024 - (63-dg)*(64-dg)/2;
            int mn  = (dg-31) > 0 ? (dg-31) : 0;
            int off = ((dg&1)==0) ? (i-mn) : (j-mn);
            int pos = cum + off;
            int c   = ((dg&1)==0) ? ((j==dg)?1:4) : ((i==dg)?4:1);
            g_order[2*LL+pos] = t; g_code[2*LL+pos] = c;
        }
        // k=3: zigzag, column-mirrored: grid idx t=(i,jj) corresponds to j2=31-jj
        {
            int j2  = 31 - j;
            int dg  = i + j2;
            int cum = (dg<=31) ? dg*(dg+1)/2 : 1024 - (63-dg)*(64-dg)/2;
            int mn  = (dg-31) > 0 ? (dg-31) : 0;
            int off = ((dg&1)==0) ? (i-mn) : (j2-mn);
            int pos = cum + off;
            int c   = ((dg&1)==0) ? ((j2==dg)?1:4) : ((i==dg)?4:1);
            g_order[3*LL+pos] = t; g_code[3*LL+pos] = c;
        }
    }
}

// ---------------- generic 64x64 tiled fp32 GEMM (C = A@B) ----------------
// mode 0: A=Aext(x), C=g_xz ; mode 1: A=g_t, C=Cext(d_out)
__global__ void __launch_bounds__(256) ss2d_gemm(
    const float* __restrict__ Aext, const float* __restrict__ Bext,
    float* __restrict__ Cext, int M, int N, int K, int mode)
{
    const float* A = (mode==0) ? Aext : g_t;
    float*       C = (mode==0) ? g_xz : Cext;
    __shared__ float As[16][65];
    __shared__ float Bs[16][64];
    int tid = threadIdx.x;
    int tx = tid & 15, ty = tid >> 4;
    int row0 = blockIdx.y*64, col0 = blockIdx.x*64;
    float acc[4][4];
    #pragma unroll
    for (int i=0;i<4;i++)
        #pragma unroll
        for (int j=0;j<4;j++) acc[i][j]=0.f;

    for (int k0=0;k0<K;k0+=16) {
        #pragma unroll
        for (int r=0;r<4;r++) {
            int idx = tid + r*256;
            int m  = idx >> 4, kk = idx & 15;
            As[kk][m] = A[(size_t)(row0+m)*K + k0+kk];
            int kk2 = idx >> 6, nn2 = idx & 63;
            Bs[kk2][nn2] = Bext[(size_t)(k0+kk2)*N + col0+nn2];
        }
        __syncthreads();
        #pragma unroll
        for (int kk=0;kk<16;kk++) {
            float a[4], bv[4];
            #pragma unroll
            for (int i=0;i<4;i++) a[i]=As[kk][ty*4+i];
            #pragma unroll
            for (int j=0;j<4;j++) bv[j]=Bs[kk][tx*4+j];
            #pragma unroll
            for (int i=0;i<4;i++)
                #pragma unroll
                for (int j=0;j<4;j++) acc[i][j] = fmaf(a[i], bv[j], acc[i][j]);
        }
        __syncthreads();
    }
    #pragma unroll
    for (int i=0;i<4;i++)
        #pragma unroll
        for (int j=0;j<4;j++)
            C[(size_t)(row0+ty*4+i)*N + col0+tx*4+j] = acc[i][j];
}

// ---------------- pw1: h1[b][m][l] = bias[m] + sum_e xm[b][l][e]*w1[m][e] -----
__global__ void __launch_bounds__(256) ss2d_pw1(const float* __restrict__ w1, const float* __restrict__ b1)
{
    __shared__ float xs[16][257];
    __shared__ float ws[256][16];   // ws[e][m]
    int tid = threadIdx.x;
    int row0 = blockIdx.x*16;       // global (b*1024+l) row
    for (int idx = tid; idx < 4096; idx += 256) {
        int m = idx >> 8, e = idx & 255;
        ws[e][m] = w1[m*256 + e];
    }
    for (int idx = tid; idx < 4096; idx += 256) {
        int r = idx >> 8, e = idx & 255;
        xs[r][e] = g_xz[(size_t)(row0+r)*512 + e];
    }
    __syncthreads();
    int m = tid >> 4, r = tid & 15;
    float acc = b1[m];
    #pragma unroll 8
    for (int e=0;e<256;e++) acc = fmaf(xs[r][e], ws[e][m], acc);
    int grow = row0 + r;
    int b = grow >> 10, l = grow & 1023;
    g_h1[((b*MIDC+m)<<10) + l] = acc;
}

// ---------------- depthwise 3x3, pad 1 ----------------
__global__ void ss2d_dw(const float* __restrict__ dw_w)
{
    int gid = blockIdx.x*256 + threadIdx.x;   // 32768 = b*m*32*32
    int j = gid & 31, i = (gid>>5)&31, m = (gid>>10)&15, b = gid>>14;
    const float* w  = dw_w + m*9;
    const float* in = g_h1 + ((b*MIDC+m)<<10);
    float acc = 0.f;
    #pragma unroll
    for (int a=0;a<3;a++) {
        int ii = i + a - 1;
        if (ii < 0 || ii > 31) continue;
        #pragma unroll
        for (int c=0;c<3;c++) {
            int jj = j + c - 1;
            if (jj < 0 || jj > 31) continue;
            acc = fmaf(w[a*3+c], in[ii*32+jj], acc);
        }
    }
    g_h2[gid] = acc;
}

// ---------------- pw2 + silu -> x_conv ----------------
__global__ void ss2d_pw2(const float* __restrict__ w2)
{
    int bl = blockIdx.x;            // b*1024+l
    int e  = threadIdx.x;
    int b  = bl >> 10, l = bl & 1023;
    __shared__ float hs[16];
    if (e < 16) hs[e] = g_h2[((b*MIDC+e)<<10) + l];
    __syncthreads();
    float acc = 0.f;
    #pragma unroll
    for (int m=0;m<16;m++) acc = fmaf(w2[e*16+m], hs[m], acc);
    g_xconv[(size_t)bl*EE + e] = acc * sigmoidf_(acc);
}

// ---------------- x_dbl = x_conv @ x_proj_w (E x 40) -> dt_lr, B, C ----------
__global__ void ss2d_xdbl(const float* __restrict__ xw)
{
    int gid = blockIdx.x*256 + threadIdx.x;   // 2048*40 = 81920 exactly
    int c  = gid % 40;
    int bl = gid / 40;
    const float* xr = g_xconv + (size_t)bl*EE;
    float acc = 0.f;
    #pragma unroll 8
    for (int e=0;e<256;e++) acc = fmaf(xr[e], xw[e*40+c], acc);
    if      (c < 8)  g_dtlr[bl*RR + c]        = acc;
    else if (c < 24) g_Bssm[bl*NN + (c-8)]    = acc;
    else             g_Cssm[bl*NN + (c-24)]   = acc;
}

// ---------------- delta = softplus(dt_lr@dt_proj_w + 2*dt_proj_b) ------------
__global__ void ss2d_delta(const float* __restrict__ dtw, const float* __restrict__ dtb)
{
    int bl = blockIdx.x;
    int e  = threadIdx.x;
    __shared__ float ds[8];
    if (e < 8) ds[e] = g_dtlr[bl*RR + e];
    __syncthreads();
    float acc = 2.f*dtb[e];
    #pragma unroll
    for (int r=0;r<8;r++) acc = fmaf(ds[r], dtw[r*256+e], acc);
    // stable softplus
    float sp = fmaxf(acc, 0.f) + log1pf(__expf(-fabsf(acc)));
    g_delta[(size_t)bl*EE + e] = sp;
}

// ---------------- gather (delta,u) into scan order ----------------
__global__ void ss2d_gather_du()
{
    int pkb = blockIdx.x;                 // (k*2+b)*1024 + p
    int e = threadIdx.x;
    int p  = pkb & 1023;
    int kb = pkb >> 10;
    int b  = kb & 1, k = kb >> 1;
    int idx = g_order[k*LL + p];
    size_t src = ((size_t)(b*LL + idx))*EE + e;
    g_du[(size_t)pkb*EE + e] = make_float2(g_delta[src], g_xconv[src]);
}

// ---------------- gather (B+dirB, C) into scan order ----------------
__global__ void ss2d_gather_bc(const float* __restrict__ dirB)
{
    int gid = blockIdx.x*256 + threadIdx.x;   // 4*2*1024*16 = 131072
    int nn = gid & 15;
    int p  = (gid >> 4) & 1023;
    int kb = gid >> 14;
    int b  = kb & 1, k = kb >> 1;
    int idx = g_order[k*LL + p];
    int cd  = (p > 0) ? g_code[k*LL + p - 1] : 0;
    float Bv = g_Bssm[(b*LL+idx)*NN + nn] + dirB[cd*NN + nn];
    float Cv = g_Cssm[(b*LL+idx)*NN + nn];
    g_bc[gid] = make_float2(Bv, Cv);
}

// ---------------- the scan: one thread per (b,k,e,n), warp = 2 e-channels ----
#define SS2D_LOAD8(DB, BBUF, P0)                                              \
    do { _Pragma("unroll")                                                    \
        for (int t_=0;t_<8;t_++) {                                            \
            DB[t_]   = __ldg(duP + (size_t)((P0)+t_)*EE);                     \
            BBUF[t_] = __ldg(bcP + (size_t)((P0)+t_)*NN);                     \
        } } while(0)

#define SS2D_STEP8(DB, BBUF, P0)                                              \
    do { _Pragma("unroll")                                                    \
        for (int t_=0;t_<8;t_++) {                                            \
            float dlt = DB[t_].x, uu = DB[t_].y;                              \
            float a_  = __expf(dlt * acoef);                                  \
            h = fmaf(a_, h, dlt*uu*BBUF[t_].x);                               \
            float py = h * BBUF[t_].y;                                        \
            py += __shfl_xor_sync(0xffffffffu, py, 1);                        \
            py += __shfl_xor_sync(0xffffffffu, py, 2);                        \
            py += __shfl_xor_sync(0xffffffffu, py, 4);                        \
            py += __shfl_xor_sync(0xffffffffu, py, 8);                        \
            if (n == 0) yoP[(size_t)((P0)+t_)*EE] = fmaf(Dv, uu, py);         \
        } } while(0)

__global__ void __launch_bounds__(256) ss2d_scan(const float* __restrict__ Dp)
{
    int w    = (blockIdx.x*256 + threadIdx.x) >> 5;   // 0..1023
    int lane = threadIdx.x & 31;
    int n    = lane & 15, esub = lane >> 4;
    int epair = w & 127;
    int k     = (w >> 7) & 3;
    int b     = w >> 9;
    int e  = epair*2 + esub;
    int kb = k*2 + b;
    const float2* duP = g_du + (size_t)kb*LL*EE + e;
    const float2* bcP = g_bc + (size_t)kb*LL*NN + n;
    float*        yoP = g_yo + (size_t)kb*LL*EE + e;
    float acoef = g_A[e*NN + n];
    float Dv    = Dp[e];
    float h = 0.f;

    float2 d0[8], b0[8], d1[8], b1[8];
    SS2D_LOAD8(d0, b0, 0);
    for (int c=0;c<64;c++) {
        int p0 = c*16;
        SS2D_LOAD8(d1, b1, p0+8);
        SS2D_STEP8(d0, b0, p0);
        if (c < 63) SS2D_LOAD8(d0, b0, p0+16);
        SS2D_STEP8(d1, b1, p0+8);
    }
}

// ---------------- recombine: y_re[m] = sum_k y_scan[k][o_k[m]]; * silu(z) ----
__global__ void ss2d_final()
{
    int bm = blockIdx.x;                 // b*1024 + m
    int e  = threadIdx.x;
    int b  = bm >> 10, m = bm & 1023;
    float acc = 0.f;
    #pragma unroll
    for (int k=0;k<4;k++) {
        int p = g_order[k*LL + m];
        acc += g_yo[(((size_t)(k*2+b))*LL + p)*EE + e];
    }
    float z = g_xz[(size_t)bm*512 + 256 + e];
    g_t[(size_t)bm*EE + e] = acc * (z * sigmoidf_(z));
}

// ---------------- launch ----------------
extern "C" void kernel_launch(void* const* d_in, const int* in_sizes, int n_in,
                              void* d_out, int out_size)
{
    const float* x          = (const float*)d_in[0];
    const float* in_proj_w  = (const float*)d_in[1];
    const float* pw1_w      = (const float*)d_in[2];
    const float* pw1_b      = (const float*)d_in[3];
    const float* dw_w       = (const float*)d_in[4];
    const float* pw2_w      = (const float*)d_in[5];
    const float* x_proj_w   = (const float*)d_in[6];
    const float* dt_proj_w  = (const float*)d_in[7];
    const float* dt_proj_b  = (const float*)d_in[8];
    const float* A_log      = (const float*)d_in[9];
    const float* Dp         = (const float*)d_in[10];
    const float* out_proj_w = (const float*)d_in[11];
    const float* dirB       = (const float*)d_in[12];
    float* out = (float*)d_out;

    ss2d_setup<<<16,256>>>(A_log);
    ss2d_gemm<<<dim3(8,32),256>>>(x, in_proj_w, nullptr, BB*LL, 2*EE, DIMM, 0);
    ss2d_pw1<<<128,256>>>(pw1_w, pw1_b);
    ss2d_dw<<<128,256>>>(dw_w);
    ss2d_pw2<<<BB*LL,256>>>(pw2_w);
    ss2d_xdbl<<<320,256>>>(x_proj_w);
    ss2d_delta<<<BB*LL,256>>>(dt_proj_w, dt_proj_b);
    ss2d_gather_du<<<4*BB*LL,256>>>();
    ss2d_gather_bc<<<512,256>>>(dirB);
    ss2d_scan<<<128,256>>>(Dp);
    ss2d_final<<<BB*LL,256>>>();
    ss2d_gemm<<<dim3(2,32),256>>>(nullptr, out_proj_w, out, BB*LL, DIMM, EE, 1);
}